// round 6
// baseline (speedup 1.0000x reference)
#include <cuda_runtime.h>
#include <cstdint>

// ThresholdSigmoidMask (JAX threefry, PARTITIONABLE mode — modern default):
//   key(42) = (0,42)
//   keys8[b] = threefry(0,42; 0, b)                (fold-like split)
//   sub_b    = threefry(keys8[b]; 0, 1)            (split(k,2)[1])
//   bits_b[i]= o0 ^ o1 of threefry(sub_b; 0, i)    (one 64-bit counter per element)
//   u        = bitcast((bits>>9)|0x3F800000) - 1.0
//   out[b,i] = (x[b,i] > u) ? 1 : 0
// Rejection loop accepts the first draw (tolerance ≈ 5 sigma of mask-mean noise).

#define N_PER_BATCH 4194304u   // 2048*2048
#define BATCH       8
#define EPT         8          // elements per thread

struct SubKeys { uint32_t k0[BATCH]; uint32_t k1[BATCH]; };

// ---------------- device threefry2x32, 8 parallel chains ----------------

#define TF_ROUND(r)                                            \
    _Pragma("unroll")                                          \
    for (int _i = 0; _i < EPT; _i++) {                         \
        a[_i] += c[_i];                                        \
        c[_i] = __funnelshift_l(c[_i], c[_i], (r));            \
        c[_i] ^= a[_i];                                        \
    }

#define TF_INJECT(ka, kb, n)                                   \
    _Pragma("unroll")                                          \
    for (int _i = 0; _i < EPT; _i++) {                         \
        a[_i] += (ka);                                         \
        c[_i] += (kb) + (n);                                   \
    }

__device__ __forceinline__ float bits_to_unit_float(uint32_t bits) {
    return __uint_as_float((bits >> 9) | 0x3F800000u) - 1.0f;
}

__global__ void __launch_bounds__(256)
threshold_mask_kernel(const float* __restrict__ in, float* __restrict__ out, SubKeys sk) {
    unsigned tid  = blockIdx.x * 256u + threadIdx.x;   // 0 .. 4194303
    unsigned b    = tid >> 19;                          // 524288 threads per batch
    unsigned base = (tid & 0x7FFFFu) * EPT;             // element index within batch

    const uint32_t ks0 = sk.k0[b];
    const uint32_t ks1 = sk.k1[b];
    const uint32_t ks2 = ks0 ^ ks1 ^ 0x1BD11BDAu;

    const uint32_t c0 = base + ks1;  // x1 init base (lo counter + key1)
    uint32_t a[EPT], c[EPT];
#pragma unroll
    for (int i = 0; i < EPT; i++) {
        a[i] = ks0;        // x0 = hi counter (0) + key0
        c[i] = c0 + i;     // x1 = lo counter (element index) + key1
    }

    TF_ROUND(13) TF_ROUND(15) TF_ROUND(26) TF_ROUND(6)
    TF_INJECT(ks1, ks2, 1u)
    TF_ROUND(17) TF_ROUND(29) TF_ROUND(16) TF_ROUND(24)
    TF_INJECT(ks2, ks0, 2u)
    TF_ROUND(13) TF_ROUND(15) TF_ROUND(26) TF_ROUND(6)
    TF_INJECT(ks0, ks1, 3u)
    TF_ROUND(17) TF_ROUND(29) TF_ROUND(16) TF_ROUND(24)
    TF_INJECT(ks1, ks2, 4u)
    TF_ROUND(13) TF_ROUND(15) TF_ROUND(26) TF_ROUND(6)
    TF_INJECT(ks2, ks0, 5u)

    size_t off = (size_t)b * N_PER_BATCH + base;

    float4 x_lo = *reinterpret_cast<const float4*>(in + off);
    float4 x_hi = *reinterpret_cast<const float4*>(in + off + 4);

    float4 r_lo, r_hi;
    r_lo.x = (x_lo.x > bits_to_unit_float(a[0] ^ c[0])) ? 1.0f : 0.0f;
    r_lo.y = (x_lo.y > bits_to_unit_float(a[1] ^ c[1])) ? 1.0f : 0.0f;
    r_lo.z = (x_lo.z > bits_to_unit_float(a[2] ^ c[2])) ? 1.0f : 0.0f;
    r_lo.w = (x_lo.w > bits_to_unit_float(a[3] ^ c[3])) ? 1.0f : 0.0f;
    r_hi.x = (x_hi.x > bits_to_unit_float(a[4] ^ c[4])) ? 1.0f : 0.0f;
    r_hi.y = (x_hi.y > bits_to_unit_float(a[5] ^ c[5])) ? 1.0f : 0.0f;
    r_hi.z = (x_hi.z > bits_to_unit_float(a[6] ^ c[6])) ? 1.0f : 0.0f;
    r_hi.w = (x_hi.w > bits_to_unit_float(a[7] ^ c[7])) ? 1.0f : 0.0f;

    *reinterpret_cast<float4*>(out + off)     = r_lo;
    *reinterpret_cast<float4*>(out + off + 4) = r_hi;
}

// ---------------- host-side threefry (key-chain derivation) ----------------

static void h_threefry2x32(uint32_t k0, uint32_t k1, uint32_t x0, uint32_t x1,
                           uint32_t& o0, uint32_t& o1) {
    const uint32_t ks2 = k0 ^ k1 ^ 0x1BD11BDAu;
    auto rotl = [](uint32_t v, int r) { return (v << r) | (v >> (32 - r)); };
    auto round4 = [&](const int* rr) {
        for (int i = 0; i < 4; i++) { x0 += x1; x1 = rotl(x1, rr[i]); x1 ^= x0; }
    };
    static const int ra[4] = {13, 15, 26, 6};
    static const int rb[4] = {17, 29, 16, 24};
    x0 += k0;  x1 += k1;
    round4(ra); x0 += k1;  x1 += ks2 + 1u;
    round4(rb); x0 += ks2; x1 += k0 + 2u;
    round4(ra); x0 += k0;  x1 += k1 + 3u;
    round4(rb); x0 += k1;  x1 += ks2 + 4u;
    round4(ra); x0 += ks2; x1 += k0 + 5u;
    o0 = x0; o1 = x1;
}

extern "C" void kernel_launch(void* const* d_in, const int* in_sizes, int n_in,
                              void* d_out, int out_size) {
    (void)in_sizes; (void)n_in; (void)out_size;

    SubKeys sk;
    for (int b = 0; b < BATCH; b++) {
        // fold-like split(key(42), 8): keys8[b] = threefry(0,42; 0, b)
        uint32_t kb0, kb1;
        h_threefry2x32(0u, 42u, 0u, (uint32_t)b, kb0, kb1);
        // split(key_b, 2)[1]: sub = threefry(key_b; 0, 1)
        uint32_t s0, s1;
        h_threefry2x32(kb0, kb1, 0u, 1u, s0, s1);
        sk.k0[b] = s0;
        sk.k1[b] = s1;
    }

    const float* in  = (const float*)d_in[0];
    float*       out = (float*)d_out;

    // 8 * 2048*2048 elements / 8 per thread = 4,194,304 threads
    threshold_mask_kernel<<<16384, 256>>>(in, out, sk);
}

// round 8
// speedup vs baseline: 1.0752x; 1.0752x over previous
#include <cuda_runtime.h>
#include <cstdint>

// ThresholdSigmoidMask (JAX threefry, PARTITIONABLE mode) — verified bit-exact R6.
//   bits_b[i] = o0 ^ o1 of threefry(sub_b; 0, i);  u = bitcast((bits>>9)|0x3F800000)-1
//   out[b,i]  = (x[b,i] > u) ? 1 : 0
//
// R7/R8 optimization: kernel is alu-pipe bound (alu=91.3%, fma=22.3% @ 97us).
// SHF/LOP3 are alu-locked, but adds can issue as IMAD on the fma pipe.
// Force every threefry add through mad.lo.u32 with an opaque runtime "one"
// so ptxas cannot strength-reduce back to IADD3. Moves ~30 ops/elem alu->fma.

#define N_PER_BATCH 4194304u   // 2048*2048
#define BATCH       8
#define EPT         8          // elements per thread

struct Params { uint32_t k0[BATCH]; uint32_t k1[BATCH]; uint32_t one; };

// x*one + y with runtime 'one'==1 -> stays IMAD (fma pipe), not IADD3 (alu pipe)
__device__ __forceinline__ uint32_t madd(uint32_t x, uint32_t y, uint32_t one) {
    uint32_t r;
    asm("mad.lo.u32 %0, %1, %2, %3;" : "=r"(r) : "r"(x), "r"(one), "r"(y));
    return r;
}

#define TF_ROUND(r)                                            \
    _Pragma("unroll")                                          \
    for (int _i = 0; _i < EPT; _i++) {                         \
        a[_i] = madd(a[_i], c[_i], one);                       \
        c[_i] = __funnelshift_l(c[_i], c[_i], (r));            \
        c[_i] ^= a[_i];                                        \
    }

#define TF_INJECT(ka, kbn)                                     \
    _Pragma("unroll")                                          \
    for (int _i = 0; _i < EPT; _i++) {                         \
        a[_i] = madd(a[_i], (ka), one);                        \
        c[_i] = madd(c[_i], (kbn), one);                       \
    }

__device__ __forceinline__ float bits_to_unit_float(uint32_t bits) {
    return __uint_as_float((bits >> 9) | 0x3F800000u) - 1.0f;
}

__global__ void __launch_bounds__(256)
threshold_mask_kernel(const float* __restrict__ in, float* __restrict__ out, Params p) {
    unsigned tid  = blockIdx.x * 256u + threadIdx.x;   // 0 .. 4194303
    unsigned b    = tid >> 19;                          // 524288 threads per batch
    unsigned base = (tid & 0x7FFFFu) * EPT;             // element index within batch

    const uint32_t one = p.one;                         // == 1, opaque to ptxas
    const uint32_t ks0 = p.k0[b];
    const uint32_t ks1 = p.k1[b];
    const uint32_t ks2 = ks0 ^ ks1 ^ 0x1BD11BDAu;

    // per-thread scalar key+round constants (amortized over EPT elements)
    const uint32_t i1 = ks2 + 1u, i2 = ks0 + 2u, i3 = ks1 + 3u,
                   i4 = ks2 + 4u, i5 = ks0 + 5u;

    const uint32_t c0 = base + ks1;  // x1 init base (lo counter + key1)
    uint32_t a[EPT], c[EPT];
#pragma unroll
    for (int i = 0; i < EPT; i++) {
        a[i] = ks0;        // x0 = hi counter (0) + key0
        c[i] = c0 + i;     // x1 = lo counter (element index) + key1
    }

    TF_ROUND(13) TF_ROUND(15) TF_ROUND(26) TF_ROUND(6)
    TF_INJECT(ks1, i1)
    TF_ROUND(17) TF_ROUND(29) TF_ROUND(16) TF_ROUND(24)
    TF_INJECT(ks2, i2)
    TF_ROUND(13) TF_ROUND(15) TF_ROUND(26) TF_ROUND(6)
    TF_INJECT(ks0, i3)
    TF_ROUND(17) TF_ROUND(29) TF_ROUND(16) TF_ROUND(24)
    TF_INJECT(ks1, i4)
    TF_ROUND(13) TF_ROUND(15) TF_ROUND(26) TF_ROUND(6)
    TF_INJECT(ks2, i5)

    size_t off = (size_t)b * N_PER_BATCH + base;

    float4 x_lo = *reinterpret_cast<const float4*>(in + off);
    float4 x_hi = *reinterpret_cast<const float4*>(in + off + 4);

    float4 r_lo, r_hi;
    r_lo.x = (x_lo.x > bits_to_unit_float(a[0] ^ c[0])) ? 1.0f : 0.0f;
    r_lo.y = (x_lo.y > bits_to_unit_float(a[1] ^ c[1])) ? 1.0f : 0.0f;
    r_lo.z = (x_lo.z > bits_to_unit_float(a[2] ^ c[2])) ? 1.0f : 0.0f;
    r_lo.w = (x_lo.w > bits_to_unit_float(a[3] ^ c[3])) ? 1.0f : 0.0f;
    r_hi.x = (x_hi.x > bits_to_unit_float(a[4] ^ c[4])) ? 1.0f : 0.0f;
    r_hi.y = (x_hi.y > bits_to_unit_float(a[5] ^ c[5])) ? 1.0f : 0.0f;
    r_hi.z = (x_hi.z > bits_to_unit_float(a[6] ^ c[6])) ? 1.0f : 0.0f;
    r_hi.w = (x_hi.w > bits_to_unit_float(a[7] ^ c[7])) ? 1.0f : 0.0f;

    *reinterpret_cast<float4*>(out + off)     = r_lo;
    *reinterpret_cast<float4*>(out + off + 4) = r_hi;
}

// ---------------- host-side threefry (key-chain derivation) ----------------

static void h_threefry2x32(uint32_t k0, uint32_t k1, uint32_t x0, uint32_t x1,
                           uint32_t& o0, uint32_t& o1) {
    const uint32_t ks2 = k0 ^ k1 ^ 0x1BD11BDAu;
    auto rotl = [](uint32_t v, int r) { return (v << r) | (v >> (32 - r)); };
    auto round4 = [&](const int* rr) {
        for (int i = 0; i < 4; i++) { x0 += x1; x1 = rotl(x1, rr[i]); x1 ^= x0; }
    };
    static const int ra[4] = {13, 15, 26, 6};
    static const int rb[4] = {17, 29, 16, 24};
    x0 += k0;  x1 += k1;
    round4(ra); x0 += k1;  x1 += ks2 + 1u;
    round4(rb); x0 += ks2; x1 += k0 + 2u;
    round4(ra); x0 += k0;  x1 += k1 + 3u;
    round4(rb); x0 += k1;  x1 += ks2 + 4u;
    round4(ra); x0 += ks2; x1 += k0 + 5u;
    o0 = x0; o1 = x1;
}

extern "C" void kernel_launch(void* const* d_in, const int* in_sizes, int n_in,
                              void* d_out, int out_size) {
    (void)in_sizes; (void)n_in; (void)out_size;

    Params p;
    p.one = 1u;
    for (int b = 0; b < BATCH; b++) {
        uint32_t kb0, kb1;
        h_threefry2x32(0u, 42u, 0u, (uint32_t)b, kb0, kb1);   // split(key(42),8)[b]
        uint32_t s0, s1;
        h_threefry2x32(kb0, kb1, 0u, 1u, s0, s1);             // split(key_b,2)[1]
        p.k0[b] = s0;
        p.k1[b] = s1;
    }

    const float* in  = (const float*)d_in[0];
    float*       out = (float*)d_out;

    threshold_mask_kernel<<<16384, 256>>>(in, out, p);
}